// round 9
// baseline (speedup 1.0000x reference)
#include <cuda_runtime.h>
#include <math.h>

#define NB 4
#define NS 1000
#define NF 256
#define NT 8192

// --- constants ---
constexpr double kTwoPiD  = 6.283185307179586;
constexpr float  kOmC     = (float)(kTwoPiD / 44100.0);       // fl32(2pi/FS): reference's omega quantum
constexpr double kTCd     = (double)kOmC / kTwoPiD;           // turns per Hz per sample
constexpr float  kTCh     = (float)kTCd;
constexpr float  kTCl     = (float)(kTCd - (double)kTCh);
constexpr float  kTwoPiF  = (float)kTwoPiD;
constexpr float  kMagic   = 12582912.0f;                      // 2^23 + 2^22

// --- static scratch (16.4 MB) ---
__device__ float g_freqR[NB][NF][NS];   // omega (radians/sample), [b][f][s]
__device__ float g_ampT [NB][NF][NS];   // amplitude, [b][f][s]
__device__ float g_P    [NB][NF][NS];   // wrapped frame-START phase, turns [-0.5,0.5]
__device__ float g_Pm   [NB][NF][NS];   // wrapped MID-frame phase (after sample 15), turns

__device__ __forceinline__ float rni_magic(float x) {
    float r = __fadd_rn(x, kMagic);
    return __fadd_rn(r, -kMagic);
}
__device__ __forceinline__ float wrap_turns(float x) {
    return __fadd_rn(x, -rni_magic(x));
}

// ---------------------------------------------------------------------------
// Prep: frame-start + mid-frame phase prefixes (wrapped, turns) AND transposed
// omega / amp.  Warp w owns sine s0+w; lane l owns frames {c*32+l}.
// Frame sum closed form: (4(x[f-1]+x[f+1]) + 24 x[f]); first half: 4x[f-1]+12x[f].
// All warp collectives in uniform control flow.  XOR-swizzled smem staging.
// ---------------------------------------------------------------------------
__global__ void __launch_bounds__(256) prep_kernel(const float* __restrict__ freq,
                                                   const float* __restrict__ amp) {
    __shared__ float smP [8][256];
    __shared__ float smPm[8][256];
    __shared__ float smF [8][256];
    __shared__ float smA [8][256];

    int tid  = threadIdx.x;
    int w    = tid >> 5;
    int lane = tid & 31;

    int b  = blockIdx.x / (NS / 8);
    int s0 = (blockIdx.x % (NS / 8)) * 8;
    int s  = s0 + w;

    const float* frow = freq + ((long)b * NS + s) * NF;
    const float* arow = amp  + ((long)b * NS + s) * NF;

    float x[8], a[8];
    #pragma unroll
    for (int c = 0; c < 8; c++) {
        x[c] = frow[c * 32 + lane];
        a[c] = arow[c * 32 + lane];
    }

    float run = 0.0f;
    #pragma unroll
    for (int c = 0; c < 8; c++) {
        float xc = x[c];

        float prev_last  = __shfl_sync(0xFFFFFFFFu, x[c > 0 ? c - 1 : 0], 31);
        float next_first = __shfl_sync(0xFFFFFFFFu, x[c < 7 ? c + 1 : 7], 0);
        float xmv = __shfl_up_sync  (0xFFFFFFFFu, xc, 1);
        float xpv = __shfl_down_sync(0xFFFFFFFFu, xc, 1);
        if (lane == 0)  xmv = (c == 0) ? xc : prev_last;
        if (lane == 31) xpv = (c == 7) ? xc : next_first;

        // full-frame sum (turns, wrapped) and first-half sum
        float t  = fmaf(24.0f, xc, 4.0f * (xmv + xpv));
        float fs = fmaf(t, kTCh, t * kTCl);
        float fsw = wrap_turns(fs);

        float th = fmaf(12.0f, xc, 4.0f * xmv);
        float hs = fmaf(th, kTCh, th * kTCl);
        float hsw = wrap_turns(hs);

        // warp inclusive scan
        float inc = fsw;
        #pragma unroll
        for (int d = 1; d < 32; d <<= 1) {
            float n = __shfl_up_sync(0xFFFFFFFFu, inc, d);
            if (lane >= d) inc += n;
        }
        float excl = inc - fsw;
        float Pf = wrap_turns(run + excl);
        float Pm = wrap_turns(Pf + hsw);

        int idx = (c * 32 + lane) ^ (w << 2);
        smP [w][idx] = Pf;
        smPm[w][idx] = Pm;
        smF [w][idx] = xc * kOmC;    // radians/sample, exact reference omega
        smA [w][idx] = a[c];

        float tot = __shfl_sync(0xFFFFFFFFu, inc, 31);
        run = wrap_turns(run + tot);
    }
    __syncthreads();

    int j  = tid & 7;
    int fi = tid >> 3;
    #pragma unroll
    for (int c2 = 0; c2 < 8; c2++) {
        int f  = c2 * 32 + fi;
        int ix = f ^ (j << 2);
        g_P    [b][f][s0 + j] = smP [j][ix];
        g_Pm   [b][f][s0 + j] = smPm[j][ix];
        g_freqR[b][f][s0 + j] = smF [j][ix];
        g_ampT [b][f][s0 + j] = smA [j][ix];
    }
}

// ---------------------------------------------------------------------------
// Synth: block = (half-frame, b).  16 accumulators/thread, radians domain,
// NO per-sample wrap (|arg| <= ~15 rad, MUFU.SIN handles it).  Inner loop:
// ph+=inc; sin; fmaf; inc+=dnc; av+=dav  (5 issue slots + MUFU).
// ---------------------------------------------------------------------------
__global__ void __launch_bounds__(256) synth_kernel(float* __restrict__ out,
                                                    const float* __restrict__ initp) {
    __shared__ float red[256][17];

    int fh   = blockIdx.x;           // 0..511
    int b    = blockIdx.y;
    int f    = fh >> 1;
    int half = fh & 1;
    int tid  = threadIdx.x;

    // interp endpoints for this half
    int ia = half ? f : (f > 0 ? f - 1 : 0);
    int ib = half ? (f < NF - 1 ? f + 1 : NF - 1) : f;
    const float w0 = half ? 0.015625f : 0.515625f;   // first-sample weight

    const float* Pbase = half ? &g_Pm[b][f][0] : &g_P[b][f][0];
    const float* Xa = &g_freqR[b][ia][0];
    const float* Xb = &g_freqR[b][ib][0];
    const float* Aa = &g_ampT [b][ia][0];
    const float* Ab = &g_ampT [b][ib][0];
    const float* I0 = initp + b * NS;

    float acc[16];
    #pragma unroll
    for (int j = 0; j < 16; j++) acc[j] = 0.0f;

    for (int s = tid; s < NS; s += 256) {
        float Pt  = Pbase[s];
        float pi0 = I0[s];
        float ph  = fmaf(Pt, kTwoPiF, pi0);      // radians, |ph| ~<= pi (+init)

        float xa = Xa[s], xb = Xb[s];
        float aa = Aa[s], ab = Ab[s];

        float d   = xb - xa;
        float inc = fmaf(w0, d, xa);             // omega at first sample of half
        float dnc = d * 0.03125f;
        float da  = ab - aa;
        float av  = fmaf(w0, da, aa);
        float dav = da * 0.03125f;

        #pragma unroll
        for (int j = 0; j < 16; j++) {
            ph = __fadd_rn(ph, inc);
            acc[j] = fmaf(av, __sinf(ph), acc[j]);
            inc = __fadd_rn(inc, dnc);
            av  = __fadd_rn(av, dav);
        }
    }

    // --- reduction over 256 threads for 16 sample slots ---
    #pragma unroll
    for (int j = 0; j < 16; j++) red[tid][j] = acc[j];
    __syncthreads();

    int j = tid & 15, r = tid >> 4;              // 16 groups of 16 rows
    float p = 0.0f;
    #pragma unroll
    for (int i = 0; i < 16; i++) p += red[r * 16 + i][j];
    __syncthreads();

    ((float*)red)[r * 16 + j] = p;
    __syncthreads();

    if (tid < 16) {
        float t = 0.0f;
        #pragma unroll
        for (int g2 = 0; g2 < 16; g2++) t += ((float*)red)[g2 * 16 + tid];
        out[((long)b << 13) + (f << 5) + (half << 4) + tid] = t;
    }
}

// ---------------------------------------------------------------------------
extern "C" void kernel_launch(void* const* d_in, const int* in_sizes, int n_in,
                              void* d_out, int out_size) {
    const float* freq  = (const float*)d_in[0];   // [4,1000,256]
    const float* amp   = (const float*)d_in[1];   // [4,1000,256]
    const float* initp = (const float*)d_in[2];   // [4,1000]
    float* out = (float*)d_out;                   // [4,1,8192]
    (void)in_sizes; (void)n_in; (void)out_size;

    prep_kernel<<<NB * (NS / 8), 256>>>(freq, amp);
    synth_kernel<<<dim3(NF * 2, NB), 256>>>(out, initp);
}

// round 10
// speedup vs baseline: 1.0013x; 1.0013x over previous
#include <cuda_runtime.h>
#include <math.h>

#define NB 4
#define NS 1000
#define NF 256
#define NT 8192

// --- constants ---
constexpr double kTwoPiD  = 6.283185307179586;
constexpr float  kOmC     = (float)(kTwoPiD / 44100.0);       // fl32(2pi/FS): reference's omega quantum
constexpr double kTCd     = (double)kOmC / kTwoPiD;           // turns per Hz per sample
constexpr float  kTCh     = (float)kTCd;
constexpr float  kTCl     = (float)(kTCd - (double)kTCh);
constexpr float  kTwoPiF  = (float)kTwoPiD;
constexpr float  kMagic   = 12582912.0f;                      // 2^23 + 2^22

// --- static scratch (16.4 MB) ---
__device__ float g_freqR[NB][NF][NS];   // omega (radians/sample), [b][f][s]
__device__ float g_ampT [NB][NF][NS];   // amplitude, [b][f][s]
__device__ float g_P    [NB][NF][NS];   // wrapped frame-START phase, turns [-0.5,0.5]
__device__ float g_Pm   [NB][NF][NS];   // wrapped MID-frame phase (after sample 15), turns

__device__ __forceinline__ float rni_magic(float x) {
    float r = __fadd_rn(x, kMagic);
    return __fadd_rn(r, -kMagic);
}
__device__ __forceinline__ float wrap_turns(float x) {
    return __fadd_rn(x, -rni_magic(x));
}

// ---------------------------------------------------------------------------
// Prep: frame-start + mid-frame phase prefixes (wrapped, turns) AND transposed
// omega / amp.  Warp w owns sine s0+w; lane l owns frames {c*32+l}.
// Frame sum closed form: (4(x[f-1]+x[f+1]) + 24 x[f]); first half: 4x[f-1]+12x[f].
// All warp collectives in uniform control flow.  XOR-swizzled smem staging.
// ---------------------------------------------------------------------------
__global__ void __launch_bounds__(256) prep_kernel(const float* __restrict__ freq,
                                                   const float* __restrict__ amp) {
    __shared__ float smP [8][256];
    __shared__ float smPm[8][256];
    __shared__ float smF [8][256];
    __shared__ float smA [8][256];

    int tid  = threadIdx.x;
    int w    = tid >> 5;
    int lane = tid & 31;

    int b  = blockIdx.x / (NS / 8);
    int s0 = (blockIdx.x % (NS / 8)) * 8;
    int s  = s0 + w;

    const float* frow = freq + ((long)b * NS + s) * NF;
    const float* arow = amp  + ((long)b * NS + s) * NF;

    float x[8], a[8];
    #pragma unroll
    for (int c = 0; c < 8; c++) {
        x[c] = frow[c * 32 + lane];
        a[c] = arow[c * 32 + lane];
    }

    float run = 0.0f;
    #pragma unroll
    for (int c = 0; c < 8; c++) {
        float xc = x[c];

        float prev_last  = __shfl_sync(0xFFFFFFFFu, x[c > 0 ? c - 1 : 0], 31);
        float next_first = __shfl_sync(0xFFFFFFFFu, x[c < 7 ? c + 1 : 7], 0);
        float xmv = __shfl_up_sync  (0xFFFFFFFFu, xc, 1);
        float xpv = __shfl_down_sync(0xFFFFFFFFu, xc, 1);
        if (lane == 0)  xmv = (c == 0) ? xc : prev_last;
        if (lane == 31) xpv = (c == 7) ? xc : next_first;

        // full-frame sum (turns, wrapped) and first-half sum
        float t  = fmaf(24.0f, xc, 4.0f * (xmv + xpv));
        float fs = fmaf(t, kTCh, t * kTCl);
        float fsw = wrap_turns(fs);

        float th = fmaf(12.0f, xc, 4.0f * xmv);
        float hs = fmaf(th, kTCh, th * kTCl);
        float hsw = wrap_turns(hs);

        // warp inclusive scan
        float inc = fsw;
        #pragma unroll
        for (int d = 1; d < 32; d <<= 1) {
            float n = __shfl_up_sync(0xFFFFFFFFu, inc, d);
            if (lane >= d) inc += n;
        }
        float excl = inc - fsw;
        float Pf = wrap_turns(run + excl);
        float Pm = wrap_turns(Pf + hsw);

        int idx = (c * 32 + lane) ^ (w << 2);
        smP [w][idx] = Pf;
        smPm[w][idx] = Pm;
        smF [w][idx] = xc * kOmC;    // radians/sample, exact reference omega
        smA [w][idx] = a[c];

        float tot = __shfl_sync(0xFFFFFFFFu, inc, 31);
        run = wrap_turns(run + tot);
    }
    __syncthreads();

    int j  = tid & 7;
    int fi = tid >> 3;
    #pragma unroll
    for (int c2 = 0; c2 < 8; c2++) {
        int f  = c2 * 32 + fi;
        int ix = f ^ (j << 2);
        g_P    [b][f][s0 + j] = smP [j][ix];
        g_Pm   [b][f][s0 + j] = smPm[j][ix];
        g_freqR[b][f][s0 + j] = smF [j][ix];
        g_ampT [b][f][s0 + j] = smA [j][ix];
    }
}

// ---------------------------------------------------------------------------
// Synth: block = (half-frame, b).  16 accumulators/thread, radians domain,
// NO per-sample wrap (|arg| <= ~15 rad, MUFU.SIN handles it).  Inner loop:
// ph+=inc; sin; fmaf; inc+=dnc; av+=dav  (5 issue slots + MUFU).
// ---------------------------------------------------------------------------
__global__ void __launch_bounds__(256) synth_kernel(float* __restrict__ out,
                                                    const float* __restrict__ initp) {
    __shared__ float red[256][17];

    int fh   = blockIdx.x;           // 0..511
    int b    = blockIdx.y;
    int f    = fh >> 1;
    int half = fh & 1;
    int tid  = threadIdx.x;

    // interp endpoints for this half
    int ia = half ? f : (f > 0 ? f - 1 : 0);
    int ib = half ? (f < NF - 1 ? f + 1 : NF - 1) : f;
    const float w0 = half ? 0.015625f : 0.515625f;   // first-sample weight

    const float* Pbase = half ? &g_Pm[b][f][0] : &g_P[b][f][0];
    const float* Xa = &g_freqR[b][ia][0];
    const float* Xb = &g_freqR[b][ib][0];
    const float* Aa = &g_ampT [b][ia][0];
    const float* Ab = &g_ampT [b][ib][0];
    const float* I0 = initp + b * NS;

    float acc[16];
    #pragma unroll
    for (int j = 0; j < 16; j++) acc[j] = 0.0f;

    for (int s = tid; s < NS; s += 256) {
        float Pt  = Pbase[s];
        float pi0 = I0[s];
        float ph  = fmaf(Pt, kTwoPiF, pi0);      // radians, |ph| ~<= pi (+init)

        float xa = Xa[s], xb = Xb[s];
        float aa = Aa[s], ab = Ab[s];

        float d   = xb - xa;
        float inc = fmaf(w0, d, xa);             // omega at first sample of half
        float dnc = d * 0.03125f;
        float da  = ab - aa;
        float av  = fmaf(w0, da, aa);
        float dav = da * 0.03125f;

        #pragma unroll
        for (int j = 0; j < 16; j++) {
            ph = __fadd_rn(ph, inc);
            acc[j] = fmaf(av, __sinf(ph), acc[j]);
            inc = __fadd_rn(inc, dnc);
            av  = __fadd_rn(av, dav);
        }
    }

    // --- reduction over 256 threads for 16 sample slots ---
    #pragma unroll
    for (int j = 0; j < 16; j++) red[tid][j] = acc[j];
    __syncthreads();

    int j = tid & 15, r = tid >> 4;              // 16 groups of 16 rows
    float p = 0.0f;
    #pragma unroll
    for (int i = 0; i < 16; i++) p += red[r * 16 + i][j];
    __syncthreads();

    ((float*)red)[r * 16 + j] = p;
    __syncthreads();

    if (tid < 16) {
        float t = 0.0f;
        #pragma unroll
        for (int g2 = 0; g2 < 16; g2++) t += ((float*)red)[g2 * 16 + tid];
        out[((long)b << 13) + (f << 5) + (half << 4) + tid] = t;
    }
}

// ---------------------------------------------------------------------------
extern "C" void kernel_launch(void* const* d_in, const int* in_sizes, int n_in,
                              void* d_out, int out_size) {
    const float* freq  = (const float*)d_in[0];   // [4,1000,256]
    const float* amp   = (const float*)d_in[1];   // [4,1000,256]
    const float* initp = (const float*)d_in[2];   // [4,1000]
    float* out = (float*)d_out;                   // [4,1,8192]
    (void)in_sizes; (void)n_in; (void)out_size;

    prep_kernel<<<NB * (NS / 8), 256>>>(freq, amp);
    synth_kernel<<<dim3(NF * 2, NB), 256>>>(out, initp);
}